// round 16
// baseline (speedup 1.0000x reference)
#include <cuda_runtime.h>
#include <cuda_bf16.h>
#include <cuda_fp16.h>
#include <cstdint>

#define F 128
#define H 4
#define HF 512
#define NRBF 20
#define OUTC 384
#define NODES_MAX 20000
#define NEDGE 160000

__device__ float g_q[NODES_MAX * HF];
__device__ float g_k[NODES_MAX * HF];
__device__ float g_v[NODES_MAX * HF];
__device__ __half g_Bh[OUTC * HF];       // denseW^T fp16, [n][k]
__device__ __half g_msgh[NEDGE * HF];    // msg fp16, [e][k]
__device__ uint32_t g_wkv[NRBF * HF];    // packed {dkW, dvW} half2, [r][col]

__device__ __forceinline__ float silu_f(float x) {
    return x * __fdividef(1.f, 1.f + __expf(-x));
}
__device__ __forceinline__ uint32_t smem_u32(const void* p) {
    uint32_t a;
    asm("{ .reg .u64 t; cvta.to.shared.u64 t, %1; cvt.u32.u64 %0, t; }"
        : "=r"(a) : "l"(p));
    return a;
}
__device__ __forceinline__ void ldsm_x4(uint32_t& r0, uint32_t& r1, uint32_t& r2,
                                        uint32_t& r3, uint32_t addr) {
    asm volatile("ldmatrix.sync.aligned.m8n8.x4.shared.b16 {%0,%1,%2,%3}, [%4];"
                 : "=r"(r0), "=r"(r1), "=r"(r2), "=r"(r3) : "r"(addr));
}
// bf16 mma (for qkv)
__device__ __forceinline__ void mma16816(float* c, const uint32_t* a,
                                         uint32_t b0, uint32_t b1) {
    asm volatile(
        "mma.sync.aligned.m16n8k16.row.col.f32.bf16.bf16.f32 "
        "{%0,%1,%2,%3},{%4,%5,%6,%7},{%8,%9},{%0,%1,%2,%3};"
        : "+f"(c[0]), "+f"(c[1]), "+f"(c[2]), "+f"(c[3])
        : "r"(a[0]), "r"(a[1]), "r"(a[2]), "r"(a[3]), "r"(b0), "r"(b1));
}
// fp16 mma (for dense gemm)
__device__ __forceinline__ void mma16816h(float* c, const uint32_t* a,
                                          uint32_t b0, uint32_t b1) {
    asm volatile(
        "mma.sync.aligned.m16n8k16.row.col.f32.f16.f16.f32 "
        "{%0,%1,%2,%3},{%4,%5,%6,%7},{%8,%9},{%0,%1,%2,%3};"
        : "+f"(c[0]), "+f"(c[1]), "+f"(c[2]), "+f"(c[3])
        : "r"(a[0]), "r"(a[1]), "r"(a[2]), "r"(a[3]), "r"(b0), "r"(b1));
}
__device__ __forceinline__ void split_bf16(float x, __nv_bfloat16& hi, __nv_bfloat16& lo) {
    hi = __float2bfloat16_rn(x);
    lo = __float2bfloat16_rn(x - __bfloat162float(hi));
}
__device__ __forceinline__ void cp16(uint32_t saddr, const void* gaddr) {
    asm volatile("cp.async.cg.shared.global [%0], [%1], 16;"
                 :: "r"(saddr), "l"(gaddr));
}
#define CP_COMMIT() asm volatile("cp.async.commit_group;" ::: "memory")
#define CP_WAIT(n)  asm volatile("cp.async.wait_group %0;" :: "n"(n) : "memory")

// ---------------------------------------------------------------------------
// Kernel 1: LN + QKV via bf16x3 mma (R12 version — proven fastest),
// plus (z==3) prep blocks: denseW fp16 (b<384) and packed dk/dv weights (b==384).
// ---------------------------------------------------------------------------
#define QS_AH 0u
#define QS_AL 34816u
#define QS_BH 69632u
#define QS_BL 104448u
#define SMEM_QKV 139264

__global__ __launch_bounds__(512) void qkv_mma_kernel(
    const float* __restrict__ s_j,
    const float* __restrict__ ln_g, const float* __restrict__ ln_b,
    const float* __restrict__ Wq, const float* __restrict__ bq,
    const float* __restrict__ Wk, const float* __restrict__ bk,
    const float* __restrict__ Wv, const float* __restrict__ bv,
    const float* __restrict__ denseW,
    const float* __restrict__ dkW, const float* __restrict__ dvW,
    int n_nodes)
{
    const int t = threadIdx.x, lane = t & 31, w = t >> 5;

    if (blockIdx.z == 3) {
        int b = blockIdx.y * 157 + blockIdx.x;
        if (b < OUTC) {
            float wv = denseW[(size_t)t * OUTC + b];
            g_Bh[b * HF + t] = __float2half_rn(wv);
        } else if (b == OUTC) {
            #pragma unroll
            for (int r = 0; r < NRBF; r++) {
                __half2 p = __floats2half2_rn(dkW[r * HF + t], dvW[r * HF + t]);
                g_wkv[r * HF + t] = *(uint32_t*)&p;
            }
        }
        return;
    }

    extern __shared__ char smc[];
    const uint32_t smb = smem_u32(smc);
    const int m = blockIdx.z;
    const int node0 = blockIdx.x * 128;
    const int ncb = blockIdx.y * 128;
    const float* W = (m == 0) ? Wq : (m == 1) ? Wk : Wv;

    float4 g4 = *(const float4*)&ln_g[lane * 4];
    float4 b4 = *(const float4*)&ln_b[lane * 4];
    #pragma unroll
    for (int nn = 0; nn < 8; nn++) {
        int nl = w * 8 + nn;
        int node = node0 + nl;
        float4 x = make_float4(0.f, 0.f, 0.f, 0.f);
        if (node < n_nodes) x = *(const float4*)&s_j[(size_t)node * F + lane * 4];
        float s  = x.x + x.y + x.z + x.w;
        float s2 = x.x * x.x + x.y * x.y + x.z * x.z + x.w * x.w;
        #pragma unroll
        for (int o = 16; o; o >>= 1) {
            s  += __shfl_xor_sync(0xffffffffu, s,  o);
            s2 += __shfl_xor_sync(0xffffffffu, s2, o);
        }
        float mu = s * (1.f / F);
        float var = s2 * (1.f / F) - mu * mu;
        float rs = rsqrtf(var + 1e-5f);
        float y[4] = {(x.x - mu) * rs * g4.x + b4.x, (x.y - mu) * rs * g4.y + b4.y,
                      (x.z - mu) * rs * g4.z + b4.z, (x.w - mu) * rs * g4.w + b4.w};
        __nv_bfloat16 h0, l0, h1, l1, h2, l2, h3, l3;
        split_bf16(y[0], h0, l0); split_bf16(y[1], h1, l1);
        split_bf16(y[2], h2, l2); split_bf16(y[3], h3, l3);
        uint32_t off = (uint32_t)(nl * 136 + lane * 4) * 2u;
        __nv_bfloat162 hp0 = __halves2bfloat162(h0, h1), hp1 = __halves2bfloat162(h2, h3);
        __nv_bfloat162 lp0 = __halves2bfloat162(l0, l1), lp1 = __halves2bfloat162(l2, l3);
        uint2 hv, lv;
        hv.x = *(uint32_t*)&hp0; hv.y = *(uint32_t*)&hp1;
        lv.x = *(uint32_t*)&lp0; lv.y = *(uint32_t*)&lp1;
        *(uint2*)(smc + QS_AH + off) = hv;
        *(uint2*)(smc + QS_AL + off) = lv;
    }

    #pragma unroll
    for (int it = 0; it < 8; it++) {
        int s = it * 512 + t;
        int n = s & 127, kq = s >> 7;
        const float* wp = &W[(size_t)(kq * 4) * HF + ncb + n];
        float w0 = wp[0], w1 = wp[HF], w2 = wp[2 * HF], w3 = wp[3 * HF];
        __nv_bfloat16 h0, l0, h1, l1, h2, l2, h3, l3;
        split_bf16(w0, h0, l0); split_bf16(w1, h1, l1);
        split_bf16(w2, h2, l2); split_bf16(w3, h3, l3);
        __nv_bfloat162 hp0 = __halves2bfloat162(h0, h1), hp1 = __halves2bfloat162(h2, h3);
        __nv_bfloat162 lp0 = __halves2bfloat162(l0, l1), lp1 = __halves2bfloat162(l2, l3);
        uint32_t off = (uint32_t)(n * 136 + kq * 4) * 2u;
        uint2 hv, lv;
        hv.x = *(uint32_t*)&hp0; hv.y = *(uint32_t*)&hp1;
        lv.x = *(uint32_t*)&lp0; lv.y = *(uint32_t*)&lp1;
        *(uint2*)(smc + QS_BH + off) = hv;
        *(uint2*)(smc + QS_BL + off) = lv;
    }
    __syncthreads();

    const int wm3 = w >> 1, wn3 = w & 1;
    float acc[8][4];
    #pragma unroll
    for (int f = 0; f < 8; f++)
        #pragma unroll
        for (int q = 0; q < 4; q++) acc[f][q] = 0.f;

    const uint32_t aoff = (uint32_t)((wm3 * 16 + (lane & 15)) * 136 + (lane >> 4) * 8) * 2u;
    const uint32_t brow = (uint32_t)((lane & 7) + ((lane >> 4) & 1) * 8);
    const uint32_t bcof = (uint32_t)(((lane >> 3) & 1) * 8);

    #pragma unroll
    for (int s = 0; s < 8; s++) {
        uint32_t ah[4], al[4];
        ldsm_x4(ah[0], ah[1], ah[2], ah[3], smb + QS_AH + aoff + s * 32);
        ldsm_x4(al[0], al[1], al[2], al[3], smb + QS_AL + aoff + s * 32);
        #pragma unroll
        for (int f = 0; f < 4; f++) {
            uint32_t n0 = (uint32_t)(wn3 * 64 + f * 16);
            uint32_t boff = ((n0 + brow) * 136 + bcof) * 2u + s * 32;
            uint32_t bh[4], bl[4];
            ldsm_x4(bh[0], bh[1], bh[2], bh[3], smb + QS_BH + boff);
            ldsm_x4(bl[0], bl[1], bl[2], bl[3], smb + QS_BL + boff);
            mma16816(acc[2 * f],     ah, bh[0], bh[1]);
            mma16816(acc[2 * f + 1], ah, bh[2], bh[3]);
            mma16816(acc[2 * f],     ah, bl[0], bl[1]);
            mma16816(acc[2 * f + 1], ah, bl[2], bl[3]);
            mma16816(acc[2 * f],     al, bh[0], bh[1]);
            mma16816(acc[2 * f + 1], al, bh[2], bh[3]);
        }
    }

    float* outp = (m == 0) ? g_q : (m == 1) ? g_k : g_v;
    const float* bias = (m == 0) ? bq : (m == 1) ? bk : bv;
    const int g = lane >> 2, tig = lane & 3;
    int na = node0 + wm3 * 16 + g;
    int nb2 = na + 8;
    #pragma unroll
    for (int f = 0; f < 8; f++) {
        int col = ncb + wn3 * 64 + f * 8 + tig * 2;
        float2 b2 = *(const float2*)&bias[col];
        if (na < n_nodes)
            *(float2*)&outp[(size_t)na * HF + col] =
                make_float2(acc[f][0] + b2.x, acc[f][1] + b2.y);
        if (nb2 < n_nodes)
            *(float2*)&outp[(size_t)nb2 * HF + col] =
                make_float2(acc[f][2] + b2.x, acc[f][3] + b2.y);
    }
}

// ---------------------------------------------------------------------------
// Kernel 2: msg production. R12 structure (16-edge quarter-batches), EPC=128,
// packed weights from g_wkv. grid E/128, block 512, 3 CTAs/SM.
// smem: dkv uint32[16*512] @0 (32768B), rbf2 uint32[128*20] @32768 (10240B),
//       env f32[128] @43008 (512B), ij int[256] @43520 (1024B). total 44544B.
// ---------------------------------------------------------------------------
#define MS_DKV  0u
#define MS_RBF  32768u
#define MS_ENV  43008u
#define MS_IJ   43520u
#define SMEM_MSG 44544

__global__ __launch_bounds__(512, 3) void msg_kernel(
    const float* __restrict__ dist, const int* __restrict__ nbrs,
    const float* __restrict__ dkb, const float* __restrict__ dvb)
{
    extern __shared__ char smc[];
    uint32_t* dkv  = (uint32_t*)(smc + MS_DKV);
    uint32_t* rbf2 = (uint32_t*)(smc + MS_RBF);
    float*    env  = (float*)(smc + MS_ENV);
    int*      ij   = (int*)(smc + MS_IJ);

    const int t = threadIdx.x, lane = t & 31, w = t >> 5;
    const int e0 = blockIdx.x * 128;

    if (t < 256) ij[t] = nbrs[(size_t)e0 * 2 + t];
    if (t < 128) {
        float d = dist[e0 + t];
        env[t] = 0.5f * (cospif(d * 0.2f) + 1.f);
    }
    #pragma unroll
    for (int it = 0; it < 5; it++) {
        int s = it * 512 + t;                // 2560 = 128*20
        int e = s / NRBF, r = s % NRBF;
        float d = dist[e0 + e];
        float u = (d - (float)r * (5.f / 19.f)) * (19.f / 5.f);
        float val = __expf(-0.5f * u * u);
        __half2 p = __floats2half2_rn(val, val);
        rbf2[s] = *(uint32_t*)&p;
    }

    uint32_t wkv[NRBF];
    #pragma unroll
    for (int r = 0; r < NRBF; r++) wkv[r] = g_wkv[r * HF + t];
    const float bkf = dkb[t];
    const float bvf = dvb[t];
    __syncthreads();

    for (int qb = 0; qb < 8; qb++) {
        // B0: 16 edges via HFMA2, 4 short chains, fp32 bias + sum
        #pragma unroll 2
        for (int el = 0; el < 16; el++) {
            int e = qb * 16 + el;
            __half2 z = __floats2half2_rn(0.f, 0.f);
            __half2 a0 = z, a1 = z, a2 = z, a3 = z;
            const uint4* rp = (const uint4*)&rbf2[e * NRBF];
            #pragma unroll
            for (int r4 = 0; r4 < 5; r4++) {
                uint4 rb = rp[r4];
                a0 = __hfma2(*(__half2*)&rb.x, *(__half2*)&wkv[r4 * 4 + 0], a0);
                a1 = __hfma2(*(__half2*)&rb.y, *(__half2*)&wkv[r4 * 4 + 1], a1);
                a2 = __hfma2(*(__half2*)&rb.z, *(__half2*)&wkv[r4 * 4 + 2], a2);
                a3 = __hfma2(*(__half2*)&rb.w, *(__half2*)&wkv[r4 * 4 + 3], a3);
            }
            float2 f0 = __half22float2(a0);
            float2 f1 = __half22float2(a1);
            float2 f2 = __half22float2(a2);
            float2 f3 = __half22float2(a3);
            float sk = (f0.x + f1.x) + (f2.x + f3.x) + bkf;
            float sv = (f0.y + f1.y) + (f2.y + f3.y) + bvf;
            __half2 res = __floats2half2_rn(silu_f(sk), silu_f(sv));
            dkv[el * 512 + t] = *(uint32_t*)&res;
        }
        __syncthreads();

        // B1: warp = edge, 4 heads
        {
            int el = w;
            int e  = qb * 16 + el;
            int i  = ij[2 * e];
            int j  = ij[2 * e + 1];
            const float* qp = g_q + (size_t)i * HF;
            const float* kp = g_k + (size_t)j * HF;
            const float* vp = g_v + (size_t)j * HF;
            float envE = env[e];
            #pragma unroll
            for (int h = 0; h < H; h++) {
                int f4 = h * F + lane * 4;
                float4 q4 = *(const float4*)(qp + f4);
                float4 k4 = *(const float4*)(kp + f4);
                uint4 kv4 = *(uint4*)&dkv[el * 512 + f4];
                float2 d0 = __half22float2(*(__half2*)&kv4.x);
                float2 d1 = __half22float2(*(__half2*)&kv4.y);
                float2 d2 = __half22float2(*(__half2*)&kv4.z);
                float2 d3 = __half22float2(*(__half2*)&kv4.w);
                float s = q4.x * d0.x * k4.x + q4.y * d1.x * k4.y
                        + q4.z * d2.x * k4.z + q4.w * d3.x * k4.w;
                #pragma unroll
                for (int o = 16; o; o >>= 1) s += __shfl_xor_sync(0xffffffffu, s, o);
                float attn = silu_f(s) * envE;
                float4 v4 = *(const float4*)(vp + f4);
                __half2 hp0 = __floats2half2_rn(attn * v4.x * d0.y, attn * v4.y * d1.y);
                __half2 hp1 = __floats2half2_rn(attn * v4.z * d2.y, attn * v4.w * d3.y);
                uint2 hv;
                hv.x = *(uint32_t*)&hp0; hv.y = *(uint32_t*)&hp1;
                *(uint2*)&g_msgh[(size_t)(e0 + e) * HF + f4] = hv;
            }
        }
        __syncthreads();
    }
}

// ---------------------------------------------------------------------------
// Kernel 3: GEMM, pure fp16 single-term (unchanged — proven)
// ---------------------------------------------------------------------------
#define GST 17920u
#define G_A  0u
#define G_B  10240u
#define SMEM_GEMM (2 * 17920)

__device__ __forceinline__ void gemm_load_chunk(
    uint32_t sb, int t, int e0, int nb, int c)
{
    #pragma unroll
    for (int it = 0; it < 2; it++) {
        int s = it * 256 + t;
        int row = s >> 2, q = s & 3;
        cp16(sb + G_A + (uint32_t)(row * 80 + q * 16),
             &g_msgh[(size_t)(e0 + row) * HF + c * 32 + q * 8]);
    }
    {
        int s = t;
        if (s < 384) {
            int row = s >> 2, q = s & 3;
            cp16(sb + G_B + (uint32_t)(row * 80 + q * 16),
                 &g_Bh[(size_t)(nb + row) * HF + c * 32 + q * 8]);
        }
        s = t + 256;
        if (s < 384) {
            int row = s >> 2, q = s & 3;
            cp16(sb + G_B + (uint32_t)(row * 80 + q * 16),
                 &g_Bh[(size_t)(nb + row) * HF + c * 32 + q * 8]);
        }
    }
}

__global__ __launch_bounds__(256, 2) void gemm_kernel(
    const float* __restrict__ denseb, float* __restrict__ out)
{
    extern __shared__ char smc[];
    const uint32_t smb = smem_u32(smc);
    const int t = threadIdx.x, lane = t & 31, w = t >> 5;
    const int nb = blockIdx.x * 96;
    const int e0 = blockIdx.y * 128;

    float acc[12][4];
    #pragma unroll
    for (int f = 0; f < 12; f++)
        #pragma unroll
        for (int q = 0; q < 4; q++) acc[f][q] = 0.f;

    const uint32_t aoff = (uint32_t)((w * 16 + (lane & 15)) * 40 + (lane >> 4) * 8) * 2u;
    const uint32_t brow = (uint32_t)((lane & 7) + ((lane >> 4) & 1) * 8);
    const uint32_t bcof = (uint32_t)(((lane >> 3) & 1) * 8);

    gemm_load_chunk(smb, t, e0, nb, 0);
    CP_COMMIT();

    for (int c = 0; c < 16; c++) {
        if (c < 15) {
            gemm_load_chunk(smb + ((c + 1) & 1) * GST, t, e0, nb, c + 1);
            CP_COMMIT();
            CP_WAIT(1);
        } else {
            CP_WAIT(0);
        }
        __syncthreads();

        const uint32_t sb = smb + (c & 1) * GST;
        #pragma unroll
        for (int s = 0; s < 2; s++) {
            uint32_t ah[4];
            ldsm_x4(ah[0], ah[1], ah[2], ah[3], sb + G_A + aoff + s * 32);
            #pragma unroll
            for (int f2 = 0; f2 < 6; f2++) {
                uint32_t boff = ((f2 * 16 + brow) * 40 + bcof) * 2u + s * 32;
                uint32_t bh[4];
                ldsm_x4(bh[0], bh[1], bh[2], bh[3], sb + G_B + boff);
                mma16816h(acc[2 * f2],     ah, bh[0], bh[1]);
                mma16816h(acc[2 * f2 + 1], ah, bh[2], bh[3]);
            }
        }
        __syncthreads();
    }

    const int g = lane >> 2, tig = lane & 3;
    const size_t r0 = (size_t)(e0 + w * 16 + g) * OUTC;
    const size_t r1 = r0 + 8 * OUTC;
    #pragma unroll
    for (int f = 0; f < 12; f++) {
        int col = nb + f * 8 + tig * 2;
        float2 b2 = *(const float2*)&denseb[col];
        *(float2*)&out[r0 + col] = make_float2(acc[f][0] + b2.x, acc[f][1] + b2.y);
        *(float2*)&out[r1 + col] = make_float2(acc[f][2] + b2.x, acc[f][3] + b2.y);
    }
}

// ---------------------------------------------------------------------------
extern "C" void kernel_launch(void* const* d_in, const int* in_sizes, int n_in,
                              void* d_out, int out_size)
{
    const float* s_j    = (const float*)d_in[0];
    const float* dist   = (const float*)d_in[1];
    const int*   nbrs   = (const int*)  d_in[2];
    const float* ln_g   = (const float*)d_in[3];
    const float* ln_b   = (const float*)d_in[4];
    const float* Wq     = (const float*)d_in[5];
    const float* bq     = (const float*)d_in[6];
    const float* Wk     = (const float*)d_in[7];
    const float* bk     = (const float*)d_in[8];
    const float* Wv     = (const float*)d_in[9];
    const float* bv     = (const float*)d_in[10];
    const float* dkW    = (const float*)d_in[11];
    const float* dkb    = (const float*)d_in[12];
    const float* dvW    = (const float*)d_in[13];
    const float* dvb    = (const float*)d_in[14];
    const float* denseW = (const float*)d_in[15];
    const float* denseb = (const float*)d_in[16];
    float* out = (float*)d_out;

    int n_nodes = in_sizes[0] / F;    // 20000
    int n_edges = in_sizes[1];        // 160000

    cudaFuncSetAttribute(qkv_mma_kernel, cudaFuncAttributeMaxDynamicSharedMemorySize, SMEM_QKV);
    cudaFuncSetAttribute(msg_kernel,     cudaFuncAttributeMaxDynamicSharedMemorySize, SMEM_MSG);
    cudaFuncSetAttribute(gemm_kernel,    cudaFuncAttributeMaxDynamicSharedMemorySize, SMEM_GEMM);

    dim3 gq((n_nodes + 127) / 128, 4, 4);
    qkv_mma_kernel<<<gq, 512, SMEM_QKV>>>(s_j, ln_g, ln_b, Wq, bq, Wk, bk, Wv, bv,
                                          denseW, dkW, dvW, n_nodes);

    msg_kernel<<<n_edges / 128, 512, SMEM_MSG>>>(dist, nbrs, dkb, dvb);

    dim3 gg(4, n_edges / 128);
    gemm_kernel<<<gg, 256, SMEM_GEMM>>>(denseb, out);
}

// round 17
// speedup vs baseline: 1.6036x; 1.6036x over previous
#include <cuda_runtime.h>
#include <cuda_bf16.h>
#include <cuda_fp16.h>
#include <cstdint>

#define F 128
#define H 4
#define HF 512
#define NRBF 20
#define OUTC 384
#define NODES_MAX 20000
#define NEDGE 160000

__device__ float g_q[NODES_MAX * HF];
__device__ float g_k[NODES_MAX * HF];
__device__ float g_v[NODES_MAX * HF];
__device__ __half g_Bh[OUTC * HF];       // denseW^T fp16, [n][k]
__device__ __half g_msgh[NEDGE * HF];    // msg fp16, [e][k]

__device__ __forceinline__ float silu_f(float x) {
    return x * __fdividef(1.f, 1.f + __expf(-x));
}
__device__ __forceinline__ uint32_t smem_u32(const void* p) {
    uint32_t a;
    asm("{ .reg .u64 t; cvta.to.shared.u64 t, %1; cvt.u32.u64 %0, t; }"
        : "=r"(a) : "l"(p));
    return a;
}
__device__ __forceinline__ void ldsm_x4(uint32_t& r0, uint32_t& r1, uint32_t& r2,
                                        uint32_t& r3, uint32_t addr) {
    asm volatile("ldmatrix.sync.aligned.m8n8.x4.shared.b16 {%0,%1,%2,%3}, [%4];"
                 : "=r"(r0), "=r"(r1), "=r"(r2), "=r"(r3) : "r"(addr));
}
// bf16 mma (for qkv)
__device__ __forceinline__ void mma16816(float* c, const uint32_t* a,
                                         uint32_t b0, uint32_t b1) {
    asm volatile(
        "mma.sync.aligned.m16n8k16.row.col.f32.bf16.bf16.f32 "
        "{%0,%1,%2,%3},{%4,%5,%6,%7},{%8,%9},{%0,%1,%2,%3};"
        : "+f"(c[0]), "+f"(c[1]), "+f"(c[2]), "+f"(c[3])
        : "r"(a[0]), "r"(a[1]), "r"(a[2]), "r"(a[3]), "r"(b0), "r"(b1));
}
// fp16 mma (for dense gemm)
__device__ __forceinline__ void mma16816h(float* c, const uint32_t* a,
                                          uint32_t b0, uint32_t b1) {
    asm volatile(
        "mma.sync.aligned.m16n8k16.row.col.f32.f16.f16.f32 "
        "{%0,%1,%2,%3},{%4,%5,%6,%7},{%8,%9},{%0,%1,%2,%3};"
        : "+f"(c[0]), "+f"(c[1]), "+f"(c[2]), "+f"(c[3])
        : "r"(a[0]), "r"(a[1]), "r"(a[2]), "r"(a[3]), "r"(b0), "r"(b1));
}
__device__ __forceinline__ void split_bf16(float x, __nv_bfloat16& hi, __nv_bfloat16& lo) {
    hi = __float2bfloat16_rn(x);
    lo = __float2bfloat16_rn(x - __bfloat162float(hi));
}
__device__ __forceinline__ void cp16(uint32_t saddr, const void* gaddr) {
    asm volatile("cp.async.cg.shared.global [%0], [%1], 16;"
                 :: "r"(saddr), "l"(gaddr));
}
#define CP_COMMIT() asm volatile("cp.async.commit_group;" ::: "memory")
#define CP_WAIT(n)  asm volatile("cp.async.wait_group %0;" :: "n"(n) : "memory")

// ---------------------------------------------------------------------------
// Kernel 1: LN + QKV via bf16x3 mma, plus (z==3) denseW fp16 prep blocks.
// ---------------------------------------------------------------------------
#define QS_AH 0u
#define QS_AL 34816u
#define QS_BH 69632u
#define QS_BL 104448u
#define SMEM_QKV 139264

__global__ __launch_bounds__(512) void qkv_mma_kernel(
    const float* __restrict__ s_j,
    const float* __restrict__ ln_g, const float* __restrict__ ln_b,
    const float* __restrict__ Wq, const float* __restrict__ bq,
    const float* __restrict__ Wk, const float* __restrict__ bk,
    const float* __restrict__ Wv, const float* __restrict__ bv,
    const float* __restrict__ denseW, int n_nodes)
{
    const int t = threadIdx.x, lane = t & 31, w = t >> 5;

    if (blockIdx.z == 3) {
        int b = blockIdx.y * 157 + blockIdx.x;
        if (b < OUTC) {
            float wv = denseW[(size_t)t * OUTC + b];
            g_Bh[b * HF + t] = __float2half_rn(wv);
        }
        return;
    }

    extern __shared__ char smc[];
    const uint32_t smb = smem_u32(smc);
    const int m = blockIdx.z;
    const int node0 = blockIdx.x * 128;
    const int ncb = blockIdx.y * 128;
    const float* W = (m == 0) ? Wq : (m == 1) ? Wk : Wv;

    float4 g4 = *(const float4*)&ln_g[lane * 4];
    float4 b4 = *(const float4*)&ln_b[lane * 4];
    #pragma unroll
    for (int nn = 0; nn < 8; nn++) {
        int nl = w * 8 + nn;
        int node = node0 + nl;
        float4 x = make_float4(0.f, 0.f, 0.f, 0.f);
        if (node < n_nodes) x = *(const float4*)&s_j[(size_t)node * F + lane * 4];
        float s  = x.x + x.y + x.z + x.w;
        float s2 = x.x * x.x + x.y * x.y + x.z * x.z + x.w * x.w;
        #pragma unroll
        for (int o = 16; o; o >>= 1) {
            s  += __shfl_xor_sync(0xffffffffu, s,  o);
            s2 += __shfl_xor_sync(0xffffffffu, s2, o);
        }
        float mu = s * (1.f / F);
        float var = s2 * (1.f / F) - mu * mu;
        float rs = rsqrtf(var + 1e-5f);
        float y[4] = {(x.x - mu) * rs * g4.x + b4.x, (x.y - mu) * rs * g4.y + b4.y,
                      (x.z - mu) * rs * g4.z + b4.z, (x.w - mu) * rs * g4.w + b4.w};
        __nv_bfloat16 h0, l0, h1, l1, h2, l2, h3, l3;
        split_bf16(y[0], h0, l0); split_bf16(y[1], h1, l1);
        split_bf16(y[2], h2, l2); split_bf16(y[3], h3, l3);
        uint32_t off = (uint32_t)(nl * 136 + lane * 4) * 2u;
        __nv_bfloat162 hp0 = __halves2bfloat162(h0, h1), hp1 = __halves2bfloat162(h2, h3);
        __nv_bfloat162 lp0 = __halves2bfloat162(l0, l1), lp1 = __halves2bfloat162(l2, l3);
        uint2 hv, lv;
        hv.x = *(uint32_t*)&hp0; hv.y = *(uint32_t*)&hp1;
        lv.x = *(uint32_t*)&lp0; lv.y = *(uint32_t*)&lp1;
        *(uint2*)(smc + QS_AH + off) = hv;
        *(uint2*)(smc + QS_AL + off) = lv;
    }

    #pragma unroll
    for (int it = 0; it < 8; it++) {
        int s = it * 512 + t;
        int n = s & 127, kq = s >> 7;
        const float* wp = &W[(size_t)(kq * 4) * HF + ncb + n];
        float w0 = wp[0], w1 = wp[HF], w2 = wp[2 * HF], w3 = wp[3 * HF];
        __nv_bfloat16 h0, l0, h1, l1, h2, l2, h3, l3;
        split_bf16(w0, h0, l0); split_bf16(w1, h1, l1);
        split_bf16(w2, h2, l2); split_bf16(w3, h3, l3);
        __nv_bfloat162 hp0 = __halves2bfloat162(h0, h1), hp1 = __halves2bfloat162(h2, h3);
        __nv_bfloat162 lp0 = __halves2bfloat162(l0, l1), lp1 = __halves2bfloat162(l2, l3);
        uint32_t off = (uint32_t)(n * 136 + kq * 4) * 2u;
        uint2 hv, lv;
        hv.x = *(uint32_t*)&hp0; hv.y = *(uint32_t*)&hp1;
        lv.x = *(uint32_t*)&lp0; lv.y = *(uint32_t*)&lp1;
        *(uint2*)(smc + QS_BH + off) = hv;
        *(uint2*)(smc + QS_BL + off) = lv;
    }
    __syncthreads();

    const int wm3 = w >> 1, wn3 = w & 1;
    float acc[8][4];
    #pragma unroll
    for (int f = 0; f < 8; f++)
        #pragma unroll
        for (int q = 0; q < 4; q++) acc[f][q] = 0.f;

    const uint32_t aoff = (uint32_t)((wm3 * 16 + (lane & 15)) * 136 + (lane >> 4) * 8) * 2u;
    const uint32_t brow = (uint32_t)((lane & 7) + ((lane >> 4) & 1) * 8);
    const uint32_t bcof = (uint32_t)(((lane >> 3) & 1) * 8);

    #pragma unroll
    for (int s = 0; s < 8; s++) {
        uint32_t ah[4], al[4];
        ldsm_x4(ah[0], ah[1], ah[2], ah[3], smb + QS_AH + aoff + s * 32);
        ldsm_x4(al[0], al[1], al[2], al[3], smb + QS_AL + aoff + s * 32);
        #pragma unroll
        for (int f = 0; f < 4; f++) {
            uint32_t n0 = (uint32_t)(wn3 * 64 + f * 16);
            uint32_t boff = ((n0 + brow) * 136 + bcof) * 2u + s * 32;
            uint32_t bh[4], bl[4];
            ldsm_x4(bh[0], bh[1], bh[2], bh[3], smb + QS_BH + boff);
            ldsm_x4(bl[0], bl[1], bl[2], bl[3], smb + QS_BL + boff);
            mma16816(acc[2 * f],     ah, bh[0], bh[1]);
            mma16816(acc[2 * f + 1], ah, bh[2], bh[3]);
            mma16816(acc[2 * f],     ah, bl[0], bl[1]);
            mma16816(acc[2 * f + 1], ah, bl[2], bl[3]);
            mma16816(acc[2 * f],     al, bh[0], bh[1]);
            mma16816(acc[2 * f + 1], al, bh[2], bh[3]);
        }
    }

    float* outp = (m == 0) ? g_q : (m == 1) ? g_k : g_v;
    const float* bias = (m == 0) ? bq : (m == 1) ? bk : bv;
    const int g = lane >> 2, tig = lane & 3;
    int na = node0 + wm3 * 16 + g;
    int nb2 = na + 8;
    #pragma unroll
    for (int f = 0; f < 8; f++) {
        int col = ncb + wn3 * 64 + f * 8 + tig * 2;
        float2 b2 = *(const float2*)&bias[col];
        if (na < n_nodes)
            *(float2*)&outp[(size_t)na * HF + col] =
                make_float2(acc[f][0] + b2.x, acc[f][1] + b2.y);
        if (nb2 < n_nodes)
            *(float2*)&outp[(size_t)nb2 * HF + col] =
                make_float2(acc[f][2] + b2.x, acc[f][3] + b2.y);
    }
}

// ---------------------------------------------------------------------------
// Kernel 2: msg production. HFMA2-packed dk/dv, 3 CTAs/SM.
// smem: dkv uint32[16*512] @0 (32768B), rbf2 uint32[64*20] @32768 (5120B),
//       env f32[64] @37888, ij int[128] @38144. total 38656B.
// ---------------------------------------------------------------------------
#define MS_DKV  0u
#define MS_RBF  32768u
#define MS_ENV  37888u
#define MS_IJ   38144u
#define SMEM_MSG 38656

__global__ __launch_bounds__(512, 3) void msg_kernel(
    const float* __restrict__ dist, const int* __restrict__ nbrs,
    const float* __restrict__ dkW, const float* __restrict__ dkb,
    const float* __restrict__ dvW, const float* __restrict__ dvb)
{
    extern __shared__ char smc[];
    uint32_t* dkv  = (uint32_t*)(smc + MS_DKV);
    uint32_t* rbf2 = (uint32_t*)(smc + MS_RBF);
    float*    env  = (float*)(smc + MS_ENV);
    int*      ij   = (int*)(smc + MS_IJ);

    const int t = threadIdx.x, lane = t & 31, w = t >> 5;
    const int e0 = blockIdx.x * 64;

    if (t < 128) ij[t] = nbrs[(size_t)e0 * 2 + t];
    if (t < 64) {
        float d = dist[e0 + t];
        env[t] = 0.5f * (cospif(d * 0.2f) + 1.f);
    }
    for (int s = t; s < 64 * NRBF; s += 512) {
        int e = s / NRBF, r = s % NRBF;
        float d = dist[e0 + e];
        float u = (d - (float)r * (5.f / 19.f)) * (19.f / 5.f);
        float val = __expf(-0.5f * u * u);
        __half2 p = __floats2half2_rn(val, val);
        rbf2[s] = *(uint32_t*)&p;
    }

    uint32_t wkv[NRBF];
    #pragma unroll
    for (int r = 0; r < NRBF; r++) {
        __half2 p = __floats2half2_rn(dkW[r * HF + t], dvW[r * HF + t]);
        wkv[r] = *(uint32_t*)&p;
    }
    __half2 bias2 = __floats2half2_rn(dkb[t], dvb[t]);
    __syncthreads();

    for (int qb = 0; qb < 4; qb++) {
        // B0: dk/dv via HFMA2, 16 edges
        #pragma unroll 2
        for (int el = 0; el < 16; el++) {
            int e = qb * 16 + el;
            __half2 acc0 = bias2;
            __half2 acc1 = __floats2half2_rn(0.f, 0.f);
            const uint4* rp = (const uint4*)&rbf2[e * NRBF];
            #pragma unroll
            for (int r4 = 0; r4 < 5; r4++) {
                uint4 rb = rp[r4];
                acc0 = __hfma2(*(__half2*)&rb.x, *(__half2*)&wkv[r4 * 4 + 0], acc0);
                acc1 = __hfma2(*(__half2*)&rb.y, *(__half2*)&wkv[r4 * 4 + 1], acc1);
                acc0 = __hfma2(*(__half2*)&rb.z, *(__half2*)&wkv[r4 * 4 + 2], acc0);
                acc1 = __hfma2(*(__half2*)&rb.w, *(__half2*)&wkv[r4 * 4 + 3], acc1);
            }
            float2 f0 = __half22float2(acc0);
            float2 f1 = __half22float2(acc1);
            __half2 res = __floats2half2_rn(silu_f(f0.x + f1.x), silu_f(f0.y + f1.y));
            dkv[el * 512 + t] = *(uint32_t*)&res;
        }
        __syncthreads();

        // B1: warp = edge, 4 heads
        {
            int el = w;
            int e  = qb * 16 + el;
            int i  = ij[2 * e];
            int j  = ij[2 * e + 1];
            const float* qp = g_q + (size_t)i * HF;
            const float* kp = g_k + (size_t)j * HF;
            const float* vp = g_v + (size_t)j * HF;
            float envE = env[e];
            #pragma unroll
            for (int h = 0; h < H; h++) {
                int f4 = h * F + lane * 4;
                float4 q4 = *(const float4*)(qp + f4);
                float4 k4 = *(const float4*)(kp + f4);
                uint4 kv4 = *(uint4*)&dkv[el * 512 + f4];
                float2 d0 = __half22float2(*(__half2*)&kv4.x);  // {dk0, dv0}
                float2 d1 = __half22float2(*(__half2*)&kv4.y);
                float2 d2 = __half22float2(*(__half2*)&kv4.z);
                float2 d3 = __half22float2(*(__half2*)&kv4.w);
                float s = q4.x * d0.x * k4.x + q4.y * d1.x * k4.y
                        + q4.z * d2.x * k4.z + q4.w * d3.x * k4.w;
                #pragma unroll
                for (int o = 16; o; o >>= 1) s += __shfl_xor_sync(0xffffffffu, s, o);
                float attn = silu_f(s) * envE;
                float4 v4 = *(const float4*)(vp + f4);
                __half2 hp0 = __floats2half2_rn(attn * v4.x * d0.y, attn * v4.y * d1.y);
                __half2 hp1 = __floats2half2_rn(attn * v4.z * d2.y, attn * v4.w * d3.y);
                uint2 hv;
                hv.x = *(uint32_t*)&hp0; hv.y = *(uint32_t*)&hp1;
                *(uint2*)&g_msgh[(size_t)(e0 + e) * HF + f4] = hv;
            }
        }
        __syncthreads();
    }
}

// ---------------------------------------------------------------------------
// Kernel 3: GEMM, pure fp16 single-term (proven)
// ---------------------------------------------------------------------------
#define GST 17920u
#define G_A  0u
#define G_B  10240u
#define SMEM_GEMM (2 * 17920)

__device__ __forceinline__ void gemm_load_chunk(
    uint32_t sb, int t, int e0, int nb, int c)
{
    #pragma unroll
    for (int it = 0; it < 2; it++) {
        int s = it * 256 + t;
        int row = s >> 2, q = s & 3;
        cp16(sb + G_A + (uint32_t)(row * 80 + q * 16),
             &g_msgh[(size_t)(e0 + row) * HF + c * 32 + q * 8]);
    }
    {
        int s = t;
        if (s < 384) {
            int row = s >> 2, q = s & 3;
            cp16(sb + G_B + (uint32_t)(row * 80 + q * 16),
                 &g_Bh[(size_t)(nb + row) * HF + c * 32 + q * 8]);
        }
        s = t + 256;
        if (s < 384) {
            int row = s >> 2, q = s & 3;
            cp16(sb + G_B + (uint32_t)(row * 80 + q * 16),
                 &g_Bh[(size_t)(nb + row) * HF + c * 32 + q * 8]);
        }
    }
}

__global__ __launch_bounds__(256, 2) void gemm_kernel(
    const float* __restrict__ denseb, float* __restrict__ out)
{
    extern __shared__ char smc[];
    const uint32_t smb = smem_u32(smc);
    const int t = threadIdx.x, lane = t & 31, w = t >> 5;
    const int nb = blockIdx.x * 96;
    const int e0 = blockIdx.y * 128;

    float acc[12][4];
    #pragma unroll
    for (int f = 0; f < 12; f++)
        #pragma unroll
        for (int q = 0; q < 4; q++) acc[f][q] = 0.f;

    const uint32_t aoff = (uint32_t)((w * 16 + (lane & 15)) * 40 + (lane >> 4) * 8) * 2u;
    const uint32_t brow = (uint32_t)((lane & 7) + ((lane >> 4) & 1) * 8);
    const uint32_t bcof = (uint32_t)(((lane >> 3) & 1) * 8);

    gemm_load_chunk(smb, t, e0, nb, 0);
    CP_COMMIT();

    for (int c = 0; c < 16; c++) {
        if (c < 15) {
            gemm_load_chunk(smb + ((c + 1) & 1) * GST, t, e0, nb, c + 1);
            CP_COMMIT();
            CP_WAIT(1);
        } else {
            CP_WAIT(0);
        }
        __syncthreads();

        const uint32_t sb = smb + (c & 1) * GST;
        #pragma unroll
        for (int s = 0; s < 2; s++) {
            uint32_t ah[4];
            ldsm_x4(ah[0], ah[1], ah[2], ah[3], sb + G_A + aoff + s * 32);
            #pragma unroll
            for (int f2 = 0; f2 < 6; f2++) {
                uint32_t boff = ((f2 * 16 + brow) * 40 + bcof) * 2u + s * 32;
                uint32_t bh[4];
                ldsm_x4(bh[0], bh[1], bh[2], bh[3], sb + G_B + boff);
                mma16816h(acc[2 * f2],     ah, bh[0], bh[1]);
                mma16816h(acc[2 * f2 + 1], ah, bh[2], bh[3]);
            }
        }
        __syncthreads();
    }

    const int g = lane >> 2, tig = lane & 3;
    const size_t r0 = (size_t)(e0 + w * 16 + g) * OUTC;
    const size_t r1 = r0 + 8 * OUTC;
    #pragma unroll
    for (int f = 0; f < 12; f++) {
        int col = nb + f * 8 + tig * 2;
        float2 b2 = *(const float2*)&denseb[col];
        *(float2*)&out[r0 + col] = make_float2(acc[f][0] + b2.x, acc[f][1] + b2.y);
        *(float2*)&out[r1 + col] = make_float2(acc[f][2] + b2.x, acc[f][3] + b2.y);
    }
}

// ---------------------------------------------------------------------------
extern "C" void kernel_launch(void* const* d_in, const int* in_sizes, int n_in,
                              void* d_out, int out_size)
{
    const float* s_j    = (const float*)d_in[0];
    const float* dist   = (const float*)d_in[1];
    const int*   nbrs   = (const int*)  d_in[2];
    const float* ln_g   = (const float*)d_in[3];
    const float* ln_b   = (const float*)d_in[4];
    const float* Wq     = (const float*)d_in[5];
    const float* bq     = (const float*)d_in[6];
    const float* Wk     = (const float*)d_in[7];
    const float* bk     = (const float*)d_in[8];
    const float* Wv     = (const float*)d_in[9];
    const float* bv     = (const float*)d_in[10];
    const float* dkW    = (const float*)d_in[11];
    const float* dkb    = (const float*)d_in[12];
    const float* dvW    = (const float*)d_in[13];
    const float* dvb    = (const float*)d_in[14];
    const float* denseW = (const float*)d_in[15];
    const float* denseb = (const float*)d_in[16];
    float* out = (float*)d_out;

    int n_nodes = in_sizes[0] / F;    // 20000
    int n_edges = in_sizes[1];        // 160000

    cudaFuncSetAttribute(qkv_mma_kernel, cudaFuncAttributeMaxDynamicSharedMemorySize, SMEM_QKV);
    cudaFuncSetAttribute(msg_kernel,     cudaFuncAttributeMaxDynamicSharedMemorySize, SMEM_MSG);
    cudaFuncSetAttribute(gemm_kernel,    cudaFuncAttributeMaxDynamicSharedMemorySize, SMEM_GEMM);

    dim3 gq((n_nodes + 127) / 128, 4, 4);
    qkv_mma_kernel<<<gq, 512, SMEM_QKV>>>(s_j, ln_g, ln_b, Wq, bq, Wk, bk, Wv, bv,
                                          denseW, n_nodes);

    msg_kernel<<<n_edges / 64, 512, SMEM_MSG>>>(dist, nbrs, dkW, dkb, dvW, dvb);

    dim3 gg(4, n_edges / 128);
    gemm_kernel<<<gg, 256, SMEM_GEMM>>>(denseb, out);
}